// round 11
// baseline (speedup 1.0000x reference)
#include <cuda_runtime.h>
#include <cstdint>
#include <cstddef>

#define TS 2048
#define NB 256
#define BT (NB*TS)
typedef unsigned long long ull;

// named-barrier helpers
#define BARS(id,n) asm volatile("bar.sync %0, %1;"   :: "r"(id), "r"(n) : "memory")
#define BARA(id,n) asm volatile("bar.arrive %0, %1;" :: "r"(id), "r"(n) : "memory")

// ---------------- scratch (device globals: allocation-free) ----------------
__device__ float  g_h2[(size_t)BT * 64];      // layer-1 hidden states (B,T,64)
__device__ float  g_states[(size_t)BT * 32];  // system_states (B,T,32)
__device__ float  g_combined[BT];             // 0.7*dr + 0.3*arrhenius
__device__ float4 g_phys[NB];                 // (Ea, logA, A, 0)

// ---------------- f32x2 helpers ----------------
__device__ __forceinline__ ull pk2(float x, float y) {
    ull r; asm("mov.b64 %0,{%1,%2};" : "=l"(r) : "f"(x), "f"(y)); return r;
}
__device__ __forceinline__ ull pkb(float x) { return pk2(x, x); }
__device__ __forceinline__ ull fma2(ull a, ull b, ull c) {
    ull d; asm("fma.rn.f32x2 %0,%1,%2,%3;" : "=l"(d) : "l"(a), "l"(b), "l"(c)); return d;
}
__device__ __forceinline__ ull add2(ull a, ull b) {
    ull d; asm("add.rn.f32x2 %0,%1,%2;" : "=l"(d) : "l"(a), "l"(b)); return d;
}
__device__ __forceinline__ float2 upk(ull v) {
    float lo, hi; asm("mov.b64 {%0,%1},%2;" : "=f"(lo), "=f"(hi) : "l"(v));
    return make_float2(lo, hi);
}
__device__ __forceinline__ ull shflx64(ull v, int m) {
    return __shfl_xor_sync(0xffffffffu, v, m);
}
__device__ __forceinline__ float sigm(float x) {
    return __fdividef(1.f, 1.f + __expf(-x));
}
__device__ __forceinline__ float tanh_(float x) {
    return 1.f - __fdividef(2.f, __expf(2.f * x) + 1.f);
}
// m_if = (act_i, act_f), m_go = (act_g, act_o)
__device__ __forceinline__ float gatepost(ull m_if, ull m_go, float& c) {
    float2 pif = upk(m_if), pgo = upk(m_go);
    float gi = sigm(pif.x), gf = sigm(pif.y), gg = tanh_(pgo.x), go = sigm(pgo.y);
    c = fmaf(gf, c, gi * gg);
    return go * tanh_(c);
}

// ---------------- dummy kernel (profiler slot alignment) ----------------
__global__ void dummy_kernel() {}

// ---------------- kernel A: physics branch (B=256 tiny MLP) ----------------
__global__ void phys_kernel(const float* __restrict__ sf,
                            const float* __restrict__ W1, const float* __restrict__ b1,
                            const float* __restrict__ W2, const float* __restrict__ b2,
                            const float* __restrict__ W3, const float* __restrict__ b3) {
    int b = threadIdx.x;
    if (b >= NB) return;
    float s0 = sf[b*3+0], s1 = sf[b*3+1], s2 = sf[b*3+2];
    float p1[32];
    #pragma unroll
    for (int j = 0; j < 32; j++) {
        float a = fmaf(W1[j*3+0], s0, fmaf(W1[j*3+1], s1, fmaf(W1[j*3+2], s2, b1[j])));
        p1[j] = fmaxf(a, 0.f);
    }
    float p2[16];
    #pragma unroll
    for (int j = 0; j < 16; j++) {
        float a = b2[j];
        #pragma unroll
        for (int k = 0; k < 32; k++) a = fmaf(W2[j*32+k], p1[k], a);
        p2[j] = fmaxf(a, 0.f);
    }
    float Ea = b3[0], lA = b3[1];
    #pragma unroll
    for (int k = 0; k < 16; k++) {
        Ea = fmaf(W3[k],      p2[k], Ea);
        lA = fmaf(W3[16 + k], p2[k], lA);
    }
    g_phys[b] = make_float4(Ea, lA, __expf(lA), 0.f);
}

// ---------------- kernel B: layer-pipelined 2-layer LSTM -------------------
// 128 blocks (2 batches each) x 384 threads, 3 warp roles (one per SMSP each):
//  G1 (warps 0-3):  layer 0. lane=(h,g2). k-half split: g2 picks 33 of 66 rows,
//                   BOTH gate-pairs; xor-1 butterfly combines k-halves.
//  q0 (warps 4-7):  layer 1 Wih1@h1[j] (k-half split) + P + gatepost + H2 write.
//  q1 (warps 8-11): layer 1 Whh1@h2[j-1] (k-half split) -> full partials P.
// Barriers: 1(256) h1 ready; 2(256) H1 consumed; 3(128) G1 visibility;
//           4(256) H2 written (q0+q1); 5(256) P ready (q0+q1).
__global__ __launch_bounds__(384, 1)
void lstm_kernel(const float* __restrict__ ts,
                 const float* __restrict__ Wih0, const float* __restrict__ Whh0,
                 const float* __restrict__ bih0, const float* __restrict__ bhh0,
                 const float* __restrict__ Wih1, const float* __restrict__ Whh1,
                 const float* __restrict__ bih1, const float* __restrict__ bhh1) {
    __shared__ ull H1[2][66][2];        // [buf][row (64,65 = x)][batch], pkb packed
    __shared__ ull H2s[64][2];          // single buffer: h2[j-1] then h2[j]
    __shared__ ulonglong2 P[64][2];     // [h][batch] = (pairA_sum, pairB_sum)
    const int tid = threadIdx.x;
    const int b0  = blockIdx.x * 2;

    for (int i = tid; i < 2*66*2; i += 384) ((ull*)H1)[i] = 0;
    for (int i = tid; i < 64*2;   i += 384) ((ull*)H2s)[i] = 0;
    __syncthreads();

    if (tid < 128) {
        // ================= G1: layer 0 =================
        const int g2 = tid & 1, h = tid >> 1;
        ull wA[33], wB[33];             // pairA=(i,f), pairB=(g,o) for my 33 rows
        #pragma unroll
        for (int i = 0; i < 33; i++) {
            const int r = g2 * 33 + i;
            if (r < 64) {
                wA[i] = pk2(Whh0[h*64+r],       Whh0[(64+h)*64+r]);
                wB[i] = pk2(Whh0[(128+h)*64+r], Whh0[(192+h)*64+r]);
            } else {
                const int d = r - 64;
                wA[i] = pk2(Wih0[h*2+d],       Wih0[(64+h)*2+d]);
                wB[i] = pk2(Wih0[(128+h)*2+d], Wih0[(192+h)*2+d]);
            }
        }
        const ull biasA = pk2(bih0[h]+bhh0[h],         bih0[64+h]+bhh0[64+h]);
        const ull biasB = pk2(bih0[128+h]+bhh0[128+h], bih0[192+h]+bhh0[192+h]);

        const bool isx = (tid >= 124);
        int xd = 0, xbb = 0; float xa = 0.f, xb = 0.f;
        if (isx) {
            xd = tid & 1; xbb = (tid >> 1) & 1;
            const float* xp = ts + (size_t)(b0+xbb)*TS*2 + xd;
            H1[0][64+xd][xbb] = pkb(xp[0]);   // x[0]
            xa = xp[2];                        // x[1]
            xb = xp[4];                        // x[2]
        }
        __syncthreads();

        float c = 0.f;
        #pragma unroll 2
        for (int i = 0; i < TS; i++) {
            if (i >= 2) BARS(2, 256);          // H1[wb] free (q0 consumed it)
            const int cb = i & 1, wb = cb ^ 1;
            if (isx) {
                if (i + 1 < TS) H1[wb][64+xd][xbb] = pkb(xa);
                xa = xb;
                int t3 = i + 3; if (t3 >= TS) t3 = TS - 1;
                xb = ts[((size_t)(b0+xbb)*TS + t3)*2 + xd];
            }
            const ull (*src)[2] = &H1[cb][g2 * 33];
            ull aA0 = 0, aA1 = 0, aB0 = 0, aB1 = 0;
            #pragma unroll
            for (int k = 0; k < 33; k++) {
                ulonglong2 v = *(const ulonglong2*)&src[k][0];
                aA0 = fma2(wA[k], v.x, aA0);
                aA1 = fma2(wA[k], v.y, aA1);
                aB0 = fma2(wB[k], v.x, aB0);
                aB1 = fma2(wB[k], v.y, aB1);
            }
            // butterfly: exchange my OTHER-batch partials; keep my batch (g2)
            ull sA = g2 ? aA0 : aA1, sB = g2 ? aB0 : aB1;
            ull mA = g2 ? aA1 : aA0, mB = g2 ? aB1 : aB0;
            mA = add2(add2(mA, shflx64(sA, 1)), biasA);
            mB = add2(add2(mB, shflx64(sB, 1)), biasB);
            float hv = gatepost(mA, mB, c);
            H1[wb][h][g2] = pkb(hv);
            BARS(3, 128);                      // G1 writes visible
            BARA(1, 256);                      // signal h1[i] ready
        }
        BARS(2, 256); BARS(2, 256);            // drain final bar2 phases
    } else if (tid < 256) {
        // ================= q0: layer 1, Wih1 @ h1[j] + epilogue =================
        const int u = tid - 128;
        const int g2 = u & 1, h = u >> 1;
        ull wA[32], wB[32];
        #pragma unroll
        for (int i = 0; i < 32; i++) {
            const int k = g2 * 32 + i;
            wA[i] = pk2(Wih1[h*64+k],       Wih1[(64+h)*64+k]);
            wB[i] = pk2(Wih1[(128+h)*64+k], Wih1[(192+h)*64+k]);
        }
        const ull biasA = pk2(bih1[h]+bhh1[h],         bih1[64+h]+bhh1[64+h]);
        const ull biasB = pk2(bih1[128+h]+bhh1[128+h], bih1[192+h]+bhh1[192+h]);
        __syncthreads();

        float c = 0.f;
        float* my_h2 = g_h2 + (size_t)(b0+g2) * TS * 64 + h;
        #pragma unroll 2
        for (int j = 0; j < TS; j++) {
            BARS(1, 256);                        // wait: h1[j] ready
            const int rb1 = (j + 1) & 1;         // H1 buf holding h1[j]
            const ull (*src)[2] = &H1[rb1][g2 * 32];
            ull aA0 = 0, aA1 = 0, aB0 = 0, aB1 = 0;
            #pragma unroll
            for (int k = 0; k < 32; k++) {
                ulonglong2 v = *(const ulonglong2*)&src[k][0];
                aA0 = fma2(wA[k], v.x, aA0);
                aA1 = fma2(wA[k], v.y, aA1);
                aB0 = fma2(wB[k], v.x, aB0);
                aB1 = fma2(wB[k], v.y, aB1);
            }
            BARA(2, 256);                        // H1 consumed -> G1 may proceed
            BARS(5, 256);                        // partials P ready
            ulonglong2 pp = P[h][g2];
            ull sA = g2 ? aA0 : aA1, sB = g2 ? aB0 : aB1;
            ull mA = g2 ? aA1 : aA0, mB = g2 ? aB1 : aB0;
            mA = add2(add2(add2(mA, shflx64(sA, 1)), pp.x), biasA);
            mB = add2(add2(add2(mB, shflx64(sB, 1)), pp.y), biasB);
            float hv = gatepost(mA, mB, c);
            H2s[h][g2] = pkb(hv);
            my_h2[(size_t)j * 64] = hv;
            BARS(4, 256);                        // H2[j] visible to q1
        }
    } else {
        // ================= q1: layer 1, Whh1 @ h2[j-1] -> partials =================
        const int u = tid - 256;
        const int g2 = u & 1, h = u >> 1;
        ull wA[32], wB[32];
        #pragma unroll
        for (int i = 0; i < 32; i++) {
            const int k = g2 * 32 + i;
            wA[i] = pk2(Whh1[h*64+k],       Whh1[(64+h)*64+k]);
            wB[i] = pk2(Whh1[(128+h)*64+k], Whh1[(192+h)*64+k]);
        }
        __syncthreads();

        #pragma unroll 2
        for (int j = 0; j < TS; j++) {
            if (j > 0) BARS(4, 256);             // wait: h2[j-1] written
            const ull (*src)[2] = &H2s[g2 * 32];
            ull aA0 = 0, aA1 = 0, aB0 = 0, aB1 = 0;
            #pragma unroll
            for (int k = 0; k < 32; k++) {
                ulonglong2 v = *(const ulonglong2*)&src[k][0];
                aA0 = fma2(wA[k], v.x, aA0);
                aA1 = fma2(wA[k], v.y, aA1);
                aB0 = fma2(wB[k], v.x, aB0);
                aB1 = fma2(wB[k], v.y, aB1);
            }
            ull sA = g2 ? aA0 : aA1, sB = g2 ? aB0 : aB1;
            ull mA = g2 ? aA1 : aA0, mB = g2 ? aB1 : aB0;
            ulonglong2 pv;
            pv.x = add2(mA, shflx64(sA, 1));
            pv.y = add2(mB, shflx64(sB, 1));
            P[h][g2] = pv;
            BARS(5, 256);                        // partials ready
        }
        BARS(4, 256);                            // drain final bar4 phase
    }
}

// ---------------- kernel C: fused SE head + degradation MLP + arrhenius ----
__global__ __launch_bounds__(256)
void sedr_kernel(const float* __restrict__ ts,
                 const float* __restrict__ seW1, const float* __restrict__ seb1,
                 const float* __restrict__ seW2, const float* __restrict__ seb2,
                 const float* __restrict__ W1, const float* __restrict__ b1,
                 const float* __restrict__ W2, const float* __restrict__ b2,
                 const float* __restrict__ W3, const float* __restrict__ b3,
                 float* __restrict__ out) {
    __shared__ float sE1[32*64], sE1b[32], sE2[32*32], sE2b[32];
    __shared__ float sW1[64*35], sb1[64], sW2[32*64], sb2[32], sW3[32], sb3[1];
    const int tid = threadIdx.x;
    for (int i = tid; i < 32*64; i += 256) sE1[i] = seW1[i];
    for (int i = tid; i < 32*32; i += 256) sE2[i] = seW2[i];
    for (int i = tid; i < 64*35; i += 256) sW1[i] = W1[i];
    for (int i = tid; i < 32*64; i += 256) sW2[i] = W2[i];
    if (tid < 64) sb1[tid] = b1[tid];
    if (tid < 32) { sE1b[tid] = seb1[tid]; sE2b[tid] = seb2[tid];
                    sb2[tid] = b2[tid]; sW3[tid] = W3[tid]; }
    if (tid == 0) sb3[0] = b3[0];
    __syncthreads();

    const size_t p = (size_t)blockIdx.x * 256 + tid;
    const int b = (int)(p >> 11);

    float h2v[64];
    const float* hp = &g_h2[p * 64];
    #pragma unroll
    for (int i = 0; i < 64; i += 4) {
        float4 v = *(const float4*)&hp[i];
        h2v[i] = v.x; h2v[i+1] = v.y; h2v[i+2] = v.z; h2v[i+3] = v.w;
    }
    float s1[32];
    #pragma unroll
    for (int j = 0; j < 32; j++) {
        float a = sE1b[j];
        #pragma unroll
        for (int k = 0; k < 64; k++) a = fmaf(sE1[j*64+k], h2v[k], a);
        s1[j] = fmaxf(a, 0.f);
    }
    float st[32];
    #pragma unroll
    for (int j = 0; j < 32; j++) {
        float a = sE2b[j];
        #pragma unroll
        for (int k = 0; k < 32; k++) a = fmaf(sE2[j*32+k], s1[k], a);
        st[j] = a;
        g_states[p*32 + j] = a;
    }
    float temp = ts[p * 2];
    float4 ph = g_phys[b];
    float h1[64];
    #pragma unroll
    for (int j = 0; j < 64; j++) {
        float a = sb1[j];
        #pragma unroll
        for (int k = 0; k < 32; k++) a = fmaf(sW1[j*35+k], st[k], a);
        a = fmaf(sW1[j*35+32], temp, a);
        a = fmaf(sW1[j*35+33], ph.x, a);
        a = fmaf(sW1[j*35+34], ph.y, a);
        h1[j] = fmaxf(a, 0.f);
    }
    float dr = sb3[0];
    #pragma unroll
    for (int j = 0; j < 32; j++) {
        float a = sb2[j];
        #pragma unroll
        for (int k = 0; k < 64; k++) a = fmaf(sW2[j*64+k], h1[k], a);
        dr = fmaf(sW3[j], fmaxf(a, 0.f), dr);
    }
    float arr = ph.z * __expf(-ph.x * 1000.f / (8.314f * (temp + 273.15f)));
    out[(size_t)BT + p] = dr;
    g_combined[p] = fmaf(0.7f, dr, 0.3f * arr);
}

// ---------------- kernel D: health scan, single-pass block scan -------------
__global__ __launch_bounds__(256)
void scan_kernel(float* __restrict__ out) {
    __shared__ float ws[8], wL[8], wU[8];
    const unsigned F = 0xffffffffu;
    int b = blockIdx.x;
    int tid = threadIdx.x, lane = tid & 31, w = tid >> 5;
    const float* cb = &g_combined[(size_t)b * TS + tid * 8];
    float c[8];
    #pragma unroll
    for (int i = 0; i < 8; i += 4) {
        float4 v = *(const float4*)(cb + i);
        c[i] = v.x; c[i+1] = v.y; c[i+2] = v.z; c[i+3] = v.w;
    }
    float s = -c[0], L = 0.f, U = 1.f;
    #pragma unroll
    for (int i = 1; i < 8; i++) {
        s -= c[i];
        L = fminf(fmaxf(L - c[i], 0.f), 1.f);
        U = fminf(fmaxf(U - c[i], 0.f), 1.f);
    }
    #pragma unroll
    for (int d = 1; d < 32; d <<= 1) {
        float ps = __shfl_up_sync(F, s, d);
        float pL = __shfl_up_sync(F, L, d);
        float pU = __shfl_up_sync(F, U, d);
        if (lane >= d) {
            float ns = ps + s;
            float nL = fminf(fmaxf(pL + s, L), U);
            float nU = fminf(fmaxf(pU + s, L), U);
            s = ns; L = nL; U = nU;
        }
    }
    if (lane == 31) { ws[w] = s; wL[w] = L; wU[w] = U; }
    __syncthreads();
    if (tid == 0) {
        float es = 0.f, eL = -1e30f, eU = 1e30f;
        #pragma unroll
        for (int i = 0; i < 8; i++) {
            float as = ws[i], aL = wL[i], aU = wU[i];
            ws[i] = es; wL[i] = eL; wU[i] = eU;
            float ns = es + as;
            float nL = fminf(fmaxf(eL + as, aL), aU);
            float nU = fminf(fmaxf(eU + as, aL), aU);
            es = ns; eL = nL; eU = nU;
        }
    }
    __syncthreads();
    float xs = __shfl_up_sync(F, s, 1);
    float xL = __shfl_up_sync(F, L, 1);
    float xU = __shfl_up_sync(F, U, 1);
    if (lane == 0) { xs = 0.f; xL = -1e30f; xU = 1e30f; }
    float es = ws[w], eL = wL[w], eU = wU[w];
    float t2s = es + xs;
    float t2L = fminf(fmaxf(eL + xs, xL), xU);
    float t2U = fminf(fmaxf(eU + xs, xL), xU);
    float hval = fminf(fmaxf(1.f + t2s, t2L), t2U);
    float o[8];
    #pragma unroll
    for (int i = 0; i < 8; i++) {
        hval = fminf(fmaxf(hval - c[i], 0.f), 1.f);
        o[i] = hval;
    }
    float* hb = &out[(size_t)2 * BT + (size_t)b * TS + tid * 8];
    *(float4*)(hb)     = make_float4(o[0], o[1], o[2], o[3]);
    *(float4*)(hb + 4) = make_float4(o[4], o[5], o[6], o[7]);
}

// ---------------- kernel E: RUL head ----------------
__global__ __launch_bounds__(256)
void rul_kernel(const float* __restrict__ W1, const float* __restrict__ b1,
                const float* __restrict__ W2, const float* __restrict__ b2,
                float* __restrict__ out) {
    __shared__ float sW1[32*33], sb1[32], sW2[32], sb2s[1];
    int tid = threadIdx.x;
    for (int i = tid; i < 32*33; i += 256) sW1[i] = W1[i];
    if (tid < 32) { sb1[tid] = b1[tid]; sW2[tid] = W2[tid]; }
    if (tid == 0) sb2s[0] = b2[0];
    __syncthreads();

    size_t p = (size_t)blockIdx.x * 256 + tid;
    const float* stp = &g_states[p * 32];
    float stv[32];
    #pragma unroll
    for (int i = 0; i < 32; i += 4) {
        float4 v = *(const float4*)&stp[i];
        stv[i] = v.x; stv[i+1] = v.y; stv[i+2] = v.z; stv[i+3] = v.w;
    }
    float hv = out[(size_t)2 * BT + p];
    float r = sb2s[0];
    #pragma unroll
    for (int j = 0; j < 32; j++) {
        float a = sb1[j];
        #pragma unroll
        for (int k = 0; k < 32; k++) a = fmaf(sW1[j*33+k], stv[k], a);
        a = fmaf(sW1[j*33+32], hv, a);
        r = fmaf(sW2[j], fmaxf(a, 0.f), r);
    }
    out[p] = fmaxf(r, 0.f);
}

// ---------------- launch ----------------
extern "C" void kernel_launch(void* const* d_in, const int* in_sizes, int n_in,
                              void* d_out, int out_size) {
    const float* ts = (const float*)d_in[0];
    const float* sf = (const float*)d_in[1];
    float* out = (float*)d_out;

    phys_kernel<<<1, 256>>>(sf,
        (const float*)d_in[14], (const float*)d_in[15],
        (const float*)d_in[16], (const float*)d_in[17],
        (const float*)d_in[18], (const float*)d_in[19]);

    // profiler-slot alignment: keep lstm_kernel at in-call launch index 3
    dummy_kernel<<<1, 32>>>();
    dummy_kernel<<<1, 32>>>();

    lstm_kernel<<<128, 384>>>(ts,
        (const float*)d_in[2],  (const float*)d_in[3],
        (const float*)d_in[4],  (const float*)d_in[5],
        (const float*)d_in[6],  (const float*)d_in[7],
        (const float*)d_in[8],  (const float*)d_in[9]);

    sedr_kernel<<<BT/256, 256>>>(ts,
        (const float*)d_in[10], (const float*)d_in[11],
        (const float*)d_in[12], (const float*)d_in[13],
        (const float*)d_in[20], (const float*)d_in[21],
        (const float*)d_in[22], (const float*)d_in[23],
        (const float*)d_in[24], (const float*)d_in[25], out);

    scan_kernel<<<NB, 256>>>(out);

    rul_kernel<<<BT/256, 256>>>(
        (const float*)d_in[26], (const float*)d_in[27],
        (const float*)d_in[28], (const float*)d_in[29], out);
}

// round 17
// speedup vs baseline: 1.0199x; 1.0199x over previous
#include <cuda_runtime.h>
#include <cstdint>
#include <cstddef>

#define TS 2048
#define NB 256
#define BT (NB*TS)
typedef unsigned long long ull;

// named-barrier helpers
#define BARS(id,n) asm volatile("bar.sync %0, %1;"   :: "r"(id), "r"(n) : "memory")
#define BARA(id,n) asm volatile("bar.arrive %0, %1;" :: "r"(id), "r"(n) : "memory")

// ---------------- scratch (device globals: allocation-free) ----------------
__device__ float  g_h2[(size_t)BT * 64];      // layer-1 hidden states (B,T,64)
__device__ float  g_states[(size_t)BT * 32];  // system_states (B,T,32)
__device__ float  g_combined[BT];             // 0.7*dr + 0.3*arrhenius
__device__ float4 g_phys[NB];                 // (Ea, logA, A, 0)

// ---------------- f32x2 helpers ----------------
__device__ __forceinline__ ull pk2(float x, float y) {
    ull r; asm("mov.b64 %0,{%1,%2};" : "=l"(r) : "f"(x), "f"(y)); return r;
}
__device__ __forceinline__ ull pkb(float x) { return pk2(x, x); }
__device__ __forceinline__ ull fma2(ull a, ull b, ull c) {
    ull d; asm("fma.rn.f32x2 %0,%1,%2,%3;" : "=l"(d) : "l"(a), "l"(b), "l"(c)); return d;
}
__device__ __forceinline__ ull add2(ull a, ull b) {
    ull d; asm("add.rn.f32x2 %0,%1,%2;" : "=l"(d) : "l"(a), "l"(b)); return d;
}
__device__ __forceinline__ float2 upk(ull v) {
    float lo, hi; asm("mov.b64 {%0,%1},%2;" : "=f"(lo), "=f"(hi) : "l"(v));
    return make_float2(lo, hi);
}
__device__ __forceinline__ ull shflx64(ull v, int m) {
    return __shfl_xor_sync(0xffffffffu, v, m);
}
__device__ __forceinline__ float sigm(float x) {
    return __fdividef(1.f, 1.f + __expf(-x));
}
__device__ __forceinline__ float tanh_(float x) {
    return 1.f - __fdividef(2.f, __expf(2.f * x) + 1.f);
}
// m_if = (act_i, act_f), m_go = (act_g, act_o)
__device__ __forceinline__ float gatepost(ull m_if, ull m_go, float& c) {
    float2 pif = upk(m_if), pgo = upk(m_go);
    float gi = sigm(pif.x), gf = sigm(pif.y), gg = tanh_(pgo.x), go = sigm(pgo.y);
    c = fmaf(gf, c, gi * gg);
    return go * tanh_(c);
}

// ---------------- dummy kernel (profiler slot alignment) ----------------
__global__ void dummy_kernel() {}

// ---------------- kernel A: physics branch (B=256 tiny MLP) ----------------
__global__ void phys_kernel(const float* __restrict__ sf,
                            const float* __restrict__ W1, const float* __restrict__ b1,
                            const float* __restrict__ W2, const float* __restrict__ b2,
                            const float* __restrict__ W3, const float* __restrict__ b3) {
    int b = threadIdx.x;
    if (b >= NB) return;
    float s0 = sf[b*3+0], s1 = sf[b*3+1], s2 = sf[b*3+2];
    float p1[32];
    #pragma unroll
    for (int j = 0; j < 32; j++) {
        float a = fmaf(W1[j*3+0], s0, fmaf(W1[j*3+1], s1, fmaf(W1[j*3+2], s2, b1[j])));
        p1[j] = fmaxf(a, 0.f);
    }
    float p2[16];
    #pragma unroll
    for (int j = 0; j < 16; j++) {
        float a = b2[j];
        #pragma unroll
        for (int k = 0; k < 32; k++) a = fmaf(W2[j*32+k], p1[k], a);
        p2[j] = fmaxf(a, 0.f);
    }
    float Ea = b3[0], lA = b3[1];
    #pragma unroll
    for (int k = 0; k < 16; k++) {
        Ea = fmaf(W3[k],      p2[k], Ea);
        lA = fmaf(W3[16 + k], p2[k], lA);
    }
    g_phys[b] = make_float4(Ea, lA, __expf(lA), 0.f);
}

// ---------------- kernel B: layer-pipelined 2-layer LSTM -------------------
// 128 blocks (2 batches each) x 384 threads, 3 warp roles (one per SMSP each):
//  G1 (warps 0-3):  layer 0. H1 double-buffer (depth 2, proven R10 scheme).
//  q0 (warps 4-7):  layer 1 Wih1@h1[j] + P combine + gatepost + H2/gmem write.
//  q1 (warps 8-11): layer 1 Whh1@h2[j-1] -> partials P (single buffer).
// Barriers:
//  1 (256): G1 arrive "h1[i] ready"; q0 sync.
//  2 (256): q0 arrive "H1 buf freed"; G1 sync (skip i<2; drain 2 at end).
//  3 (128): G1-internal visibility before arrive(1).
//  4 (256): q0 arrive "h2[j] stored"; q1 sync (skip j=0).      [skew<=1: safe]
//  5 (256): q1 arrive "P[j] ready";  q0 sync.                  [skew<=1: safe]
//  6 (128): q1-internal visibility before arrive(5).
//  8 (128): q0-internal visibility before arrive(4).
// Skew proof (no lost trips): q1's arrive5(j+1) is gated by its sync4(j+1),
// which needs q0's arrive4(j), which follows q0's sync5(j) — so between any
// two producer arrives the consumer has synced, and vice versa for bar4.
__global__ __launch_bounds__(384, 1)
void lstm_kernel(const float* __restrict__ ts,
                 const float* __restrict__ Wih0, const float* __restrict__ Whh0,
                 const float* __restrict__ bih0, const float* __restrict__ bhh0,
                 const float* __restrict__ Wih1, const float* __restrict__ Whh1,
                 const float* __restrict__ bih1, const float* __restrict__ bhh1) {
    __shared__ ull H1[2][66][2];        // [buf][row (64,65 = x)][batch], pkb packed
    __shared__ ull H2s[64][2];          // single buffer: h2[j-1] then h2[j]
    __shared__ ulonglong2 P[64][2];     // q1 partials: [h][batch]
    const int tid = threadIdx.x;
    const int b0  = blockIdx.x * 2;

    for (int i = tid; i < 2*66*2; i += 384) ((ull*)H1)[i] = 0;
    for (int i = tid; i < 64*2;   i += 384) ((ull*)H2s)[i] = 0;
    __syncthreads();

    if (tid < 128) {
        // ================= G1: layer 0 (verbatim R10) =================
        const int g2 = tid & 1, h = tid >> 1;
        ull w[66];
        const int rA = g2*128 + h, rB = rA + 64;
        #pragma unroll
        for (int k = 0; k < 64; k++)
            w[k] = pk2(Whh0[rA*64+k], Whh0[rB*64+k]);
        w[64] = pk2(Wih0[rA*2+0], Wih0[rB*2+0]);
        w[65] = pk2(Wih0[rA*2+1], Wih0[rB*2+1]);
        const ull bias = pk2(bih0[rA]+bhh0[rA], bih0[rB]+bhh0[rB]);

        const bool isx = (tid >= 124);
        int xd = 0, xbb = 0; float xa = 0.f, xb = 0.f;
        if (isx) {
            xd = tid & 1; xbb = (tid >> 1) & 1;
            const float* xp = ts + (size_t)(b0+xbb)*TS*2 + xd;
            H1[0][64+xd][xbb] = pkb(xp[0]);   // x[0]
            xa = xp[2];                        // x[1]
            xb = xp[4];                        // x[2]
        }
        __syncthreads();

        float c = 0.f;
        #pragma unroll 2
        for (int i = 0; i < TS; i++) {
            if (i >= 2) BARS(2, 256);          // H1[wb] free (q0 consumed it)
            const int cb = i & 1, wb = cb ^ 1;
            if (isx) {
                if (i + 1 < TS) H1[wb][64+xd][xbb] = pkb(xa);
                xa = xb;
                int t3 = i + 3; if (t3 >= TS) t3 = TS - 1;
                xb = ts[((size_t)(b0+xbb)*TS + t3)*2 + xd];
            }
            ull a0 = 0, a1 = 0, a2 = 0, a3 = 0;
            #pragma unroll
            for (int k = 0; k < 66; k += 2) {
                ulonglong2 v0 = *(const ulonglong2*)&H1[cb][k][0];
                ulonglong2 v1 = *(const ulonglong2*)&H1[cb][k+1][0];
                a0 = fma2(w[k],   v0.x, a0);  a2 = fma2(w[k],   v0.y, a2);
                a1 = fma2(w[k+1], v1.x, a1);  a3 = fma2(w[k+1], v1.y, a3);
            }
            ull m0 = add2(add2(a0, a1), bias);   // my gate-pair, batch0
            ull m1 = add2(add2(a2, a3), bias);   // my gate-pair, batch1
            ull oth  = shflx64(g2 ? m0 : m1, 1); // partner pair, MY batch
            ull mine = g2 ? m1 : m0;
            float hv = gatepost(g2 ? oth : mine, g2 ? mine : oth, c);
            H1[wb][h][g2] = pkb(hv);
            BARS(3, 128);                      // G1 writes visible
            BARA(1, 256);                      // signal h1[i] ready
        }
        BARS(2, 256); BARS(2, 256);            // drain final bar2 phases
    } else if (tid < 256) {
        // ================= q0: layer 1, Wih1 @ h1[j] + epilogue =================
        const int u = tid - 128;
        const int g2 = u & 1, h = u >> 1;
        ull w[64];
        const int rA = g2*128 + h, rB = rA + 64;
        #pragma unroll
        for (int k = 0; k < 64; k++)
            w[k] = pk2(Wih1[rA*64+k], Wih1[rB*64+k]);
        const ull bias = pk2(bih1[rA]+bhh1[rA], bih1[rB]+bhh1[rB]);
        __syncthreads();

        float c = 0.f;
        float* my_h2 = g_h2 + (size_t)(b0+g2) * TS * 64 + h;
        #pragma unroll 2
        for (int j = 0; j < TS; j++) {
            BARS(1, 256);                        // wait: h1[j] ready
            const int rb1 = (j + 1) & 1;         // H1 buf holding h1[j]
            ull a0 = 0, a1 = 0, a2 = 0, a3 = 0;
            #pragma unroll
            for (int k = 0; k < 64; k += 2) {
                ulonglong2 v0 = *(const ulonglong2*)&H1[rb1][k][0];
                ulonglong2 v1 = *(const ulonglong2*)&H1[rb1][k+1][0];
                a0 = fma2(w[k],   v0.x, a0);  a2 = fma2(w[k],   v0.y, a2);
                a1 = fma2(w[k+1], v1.x, a1);  a3 = fma2(w[k+1], v1.y, a3);
            }
            BARA(2, 256);                        // H1 slot freed -> G1 proceeds
            BARS(5, 256);                        // wait: P[j] ready (q1 arrived)
            ulonglong2 pp = P[h][g2];
            ull m0 = add2(add2(add2(a0, a1), pp.x), bias);
            ull m1 = add2(add2(add2(a2, a3), pp.y), bias);
            ull oth  = shflx64(g2 ? m0 : m1, 1);
            ull mine = g2 ? m1 : m0;
            float hv = gatepost(g2 ? oth : mine, g2 ? mine : oth, c);
            H2s[h][g2] = pkb(hv);
            BARS(8, 128);                        // q0-internal: H2s visible
            BARA(4, 256);                        // signal h2[j] stored
            my_h2[(size_t)j * 64] = hv;          // off critical path
        }
    } else {
        // ================= q1: layer 1, Whh1 @ h2[j-1] -> partials =================
        const int u = tid - 256;
        const int g2 = u & 1, h = u >> 1;
        ull w[64];
        const int rA = g2*128 + h, rB = rA + 64;
        #pragma unroll
        for (int k = 0; k < 64; k++)
            w[k] = pk2(Whh1[rA*64+k], Whh1[rB*64+k]);
        __syncthreads();

        #pragma unroll 2
        for (int j = 0; j < TS; j++) {
            if (j > 0) BARS(4, 256);             // wait: h2[j-1] stored
            ull a0 = 0, a1 = 0, a2 = 0, a3 = 0;
            #pragma unroll
            for (int k = 0; k < 64; k += 2) {
                ulonglong2 v0 = *(const ulonglong2*)&H2s[k][0];
                ulonglong2 v1 = *(const ulonglong2*)&H2s[k+1][0];
                a0 = fma2(w[k],   v0.x, a0);  a2 = fma2(w[k],   v0.y, a2);
                a1 = fma2(w[k+1], v1.x, a1);  a3 = fma2(w[k+1], v1.y, a3);
            }
            ulonglong2 pv; pv.x = add2(a0, a1); pv.y = add2(a2, a3);
            P[h][g2] = pv;
            BARS(6, 128);                        // q1-internal: P visible
            BARA(5, 256);                        // signal P[j] ready
        }
        // final bar4 arrive from q0's j=2047 stays un-consumed: no waiter, OK.
    }
}

// ---------------- kernel C: fused SE head + degradation MLP + arrhenius ----
__global__ __launch_bounds__(256)
void sedr_kernel(const float* __restrict__ ts,
                 const float* __restrict__ seW1, const float* __restrict__ seb1,
                 const float* __restrict__ seW2, const float* __restrict__ seb2,
                 const float* __restrict__ W1, const float* __restrict__ b1,
                 const float* __restrict__ W2, const float* __restrict__ b2,
                 const float* __restrict__ W3, const float* __restrict__ b3,
                 float* __restrict__ out) {
    __shared__ float sE1[32*64], sE1b[32], sE2[32*32], sE2b[32];
    __shared__ float sW1[64*35], sb1[64], sW2[32*64], sb2[32], sW3[32], sb3[1];
    const int tid = threadIdx.x;
    for (int i = tid; i < 32*64; i += 256) sE1[i] = seW1[i];
    for (int i = tid; i < 32*32; i += 256) sE2[i] = seW2[i];
    for (int i = tid; i < 64*35; i += 256) sW1[i] = W1[i];
    for (int i = tid; i < 32*64; i += 256) sW2[i] = W2[i];
    if (tid < 64) sb1[tid] = b1[tid];
    if (tid < 32) { sE1b[tid] = seb1[tid]; sE2b[tid] = seb2[tid];
                    sb2[tid] = b2[tid]; sW3[tid] = W3[tid]; }
    if (tid == 0) sb3[0] = b3[0];
    __syncthreads();

    const size_t p = (size_t)blockIdx.x * 256 + tid;
    const int b = (int)(p >> 11);

    float h2v[64];
    const float* hp = &g_h2[p * 64];
    #pragma unroll
    for (int i = 0; i < 64; i += 4) {
        float4 v = *(const float4*)&hp[i];
        h2v[i] = v.x; h2v[i+1] = v.y; h2v[i+2] = v.z; h2v[i+3] = v.w;
    }
    float s1[32];
    #pragma unroll
    for (int j = 0; j < 32; j++) {
        float a = sE1b[j];
        #pragma unroll
        for (int k = 0; k < 64; k++) a = fmaf(sE1[j*64+k], h2v[k], a);
        s1[j] = fmaxf(a, 0.f);
    }
    float st[32];
    #pragma unroll
    for (int j = 0; j < 32; j++) {
        float a = sE2b[j];
        #pragma unroll
        for (int k = 0; k < 32; k++) a = fmaf(sE2[j*32+k], s1[k], a);
        st[j] = a;
        g_states[p*32 + j] = a;
    }
    float temp = ts[p * 2];
    float4 ph = g_phys[b];
    float h1[64];
    #pragma unroll
    for (int j = 0; j < 64; j++) {
        float a = sb1[j];
        #pragma unroll
        for (int k = 0; k < 32; k++) a = fmaf(sW1[j*35+k], st[k], a);
        a = fmaf(sW1[j*35+32], temp, a);
        a = fmaf(sW1[j*35+33], ph.x, a);
        a = fmaf(sW1[j*35+34], ph.y, a);
        h1[j] = fmaxf(a, 0.f);
    }
    float dr = sb3[0];
    #pragma unroll
    for (int j = 0; j < 32; j++) {
        float a = sb2[j];
        #pragma unroll
        for (int k = 0; k < 64; k++) a = fmaf(sW2[j*64+k], h1[k], a);
        dr = fmaf(sW3[j], fmaxf(a, 0.f), dr);
    }
    float arr = ph.z * __expf(-ph.x * 1000.f / (8.314f * (temp + 273.15f)));
    out[(size_t)BT + p] = dr;
    g_combined[p] = fmaf(0.7f, dr, 0.3f * arr);
}

// ---------------- kernel D: health scan, single-pass block scan -------------
__global__ __launch_bounds__(256)
void scan_kernel(float* __restrict__ out) {
    __shared__ float ws[8], wL[8], wU[8];
    const unsigned F = 0xffffffffu;
    int b = blockIdx.x;
    int tid = threadIdx.x, lane = tid & 31, w = tid >> 5;
    const float* cb = &g_combined[(size_t)b * TS + tid * 8];
    float c[8];
    #pragma unroll
    for (int i = 0; i < 8; i += 4) {
        float4 v = *(const float4*)(cb + i);
        c[i] = v.x; c[i+1] = v.y; c[i+2] = v.z; c[i+3] = v.w;
    }
    float s = -c[0], L = 0.f, U = 1.f;
    #pragma unroll
    for (int i = 1; i < 8; i++) {
        s -= c[i];
        L = fminf(fmaxf(L - c[i], 0.f), 1.f);
        U = fminf(fmaxf(U - c[i], 0.f), 1.f);
    }
    #pragma unroll
    for (int d = 1; d < 32; d <<= 1) {
        float ps = __shfl_up_sync(F, s, d);
        float pL = __shfl_up_sync(F, L, d);
        float pU = __shfl_up_sync(F, U, d);
        if (lane >= d) {
            float ns = ps + s;
            float nL = fminf(fmaxf(pL + s, L), U);
            float nU = fminf(fmaxf(pU + s, L), U);
            s = ns; L = nL; U = nU;
        }
    }
    if (lane == 31) { ws[w] = s; wL[w] = L; wU[w] = U; }
    __syncthreads();
    if (tid == 0) {
        float es = 0.f, eL = -1e30f, eU = 1e30f;
        #pragma unroll
        for (int i = 0; i < 8; i++) {
            float as = ws[i], aL = wL[i], aU = wU[i];
            ws[i] = es; wL[i] = eL; wU[i] = eU;
            float ns = es + as;
            float nL = fminf(fmaxf(eL + as, aL), aU);
            float nU = fminf(fmaxf(eU + as, aL), aU);
            es = ns; eL = nL; eU = nU;
        }
    }
    __syncthreads();
    float xs = __shfl_up_sync(F, s, 1);
    float xL = __shfl_up_sync(F, L, 1);
    float xU = __shfl_up_sync(F, U, 1);
    if (lane == 0) { xs = 0.f; xL = -1e30f; xU = 1e30f; }
    float es = ws[w], eL = wL[w], eU = wU[w];
    float t2s = es + xs;
    float t2L = fminf(fmaxf(eL + xs, xL), xU);
    float t2U = fminf(fmaxf(eU + xs, xL), xU);
    float hval = fminf(fmaxf(1.f + t2s, t2L), t2U);
    float o[8];
    #pragma unroll
    for (int i = 0; i < 8; i++) {
        hval = fminf(fmaxf(hval - c[i], 0.f), 1.f);
        o[i] = hval;
    }
    float* hb = &out[(size_t)2 * BT + (size_t)b * TS + tid * 8];
    *(float4*)(hb)     = make_float4(o[0], o[1], o[2], o[3]);
    *(float4*)(hb + 4) = make_float4(o[4], o[5], o[6], o[7]);
}

// ---------------- kernel E: RUL head ----------------
__global__ __launch_bounds__(256)
void rul_kernel(const float* __restrict__ W1, const float* __restrict__ b1,
                const float* __restrict__ W2, const float* __restrict__ b2,
                float* __restrict__ out) {
    __shared__ float sW1[32*33], sb1[32], sW2[32], sb2s[1];
    int tid = threadIdx.x;
    for (int i = tid; i < 32*33; i += 256) sW1[i] = W1[i];
    if (tid < 32) { sb1[tid] = b1[tid]; sW2[tid] = W2[tid]; }
    if (tid == 0) sb2s[0] = b2[0];
    __syncthreads();

    size_t p = (size_t)blockIdx.x * 256 + tid;
    const float* stp = &g_states[p * 32];
    float stv[32];
    #pragma unroll
    for (int i = 0; i < 32; i += 4) {
        float4 v = *(const float4*)&stp[i];
        stv[i] = v.x; stv[i+1] = v.y; stv[i+2] = v.z; stv[i+3] = v.w;
    }
    float hv = out[(size_t)2 * BT + p];
    float r = sb2s[0];
    #pragma unroll
    for (int j = 0; j < 32; j++) {
        float a = sb1[j];
        #pragma unroll
        for (int k = 0; k < 32; k++) a = fmaf(sW1[j*33+k], stv[k], a);
        a = fmaf(sW1[j*33+32], hv, a);
        r = fmaf(sW2[j], fmaxf(a, 0.f), r);
    }
    out[p] = fmaxf(r, 0.f);
}

// ---------------- launch ----------------
extern "C" void kernel_launch(void* const* d_in, const int* in_sizes, int n_in,
                              void* d_out, int out_size) {
    const float* ts = (const float*)d_in[0];
    const float* sf = (const float*)d_in[1];
    float* out = (float*)d_out;

    phys_kernel<<<1, 256>>>(sf,
        (const float*)d_in[14], (const float*)d_in[15],
        (const float*)d_in[16], (const float*)d_in[17],
        (const float*)d_in[18], (const float*)d_in[19]);

    // profiler-slot alignment: keep lstm_kernel at in-call launch index 3
    dummy_kernel<<<1, 32>>>();
    dummy_kernel<<<1, 32>>>();

    lstm_kernel<<<128, 384>>>(ts,
        (const float*)d_in[2],  (const float*)d_in[3],
        (const float*)d_in[4],  (const float*)d_in[5],
        (const float*)d_in[6],  (const float*)d_in[7],
        (const float*)d_in[8],  (const float*)d_in[9]);

    sedr_kernel<<<BT/256, 256>>>(ts,
        (const float*)d_in[10], (const float*)d_in[11],
        (const float*)d_in[12], (const float*)d_in[13],
        (const float*)d_in[20], (const float*)d_in[21],
        (const float*)d_in[22], (const float*)d_in[23],
        (const float*)d_in[24], (const float*)d_in[25], out);

    scan_kernel<<<NB, 256>>>(out);

    rul_kernel<<<BT/256, 256>>>(
        (const float*)d_in[26], (const float*)d_in[27],
        (const float*)d_in[28], (const float*)d_in[29], out);
}